// round 14
// baseline (speedup 1.0000x reference)
#include <cuda_runtime.h>
#include <cuda_fp16.h>
#include <cstdint>

// Problem dims
#define NB 8
#define NH 8
#define SLQ 1024
#define SLK 1024
#define DD 512
#define HD 4096

using hf = __half;

// ---------------- device global scratch ----------------
__device__ hf g_x[(size_t)NB*SLQ*DD];
__device__ hf g_st[(size_t)NB*SLK*DD];
__device__ hf g_Wq[(size_t)NH*DD*DD];
__device__ hf g_Wk[(size_t)NH*DD*DD];
__device__ hf g_Wv[(size_t)NH*DD*DD];
__device__ hf g_Wp[(size_t)DD*HD];
__device__ hf g_QK[(size_t)128*SLQ*DD];    // single-plane Q (z<64), K (z>=64)
__device__ hf g_VT[(size_t)64*DD*SLK];
__device__ float g_S[(size_t)64*SLQ*SLK];
__device__ hf g_P[(size_t)64*SLQ*SLK];     // single-plane P
__device__ hf g_C[(size_t)NB*SLQ*HD];      // single-plane ctx

// ---------------- PTX helpers (baseline ISA only) ----------------
__device__ __forceinline__ uint32_t smem_u32(const void* p) {
    uint32_t a;
    asm("{ .reg .u64 t; cvta.to.shared.u64 t, %1; cvt.u32.u64 %0, t; }" : "=r"(a) : "l"(p));
    return a;
}
#define CP_ASYNC16(dst, src) \
    asm volatile("cp.async.cg.shared.global [%0], [%1], 16;" :: "r"(dst), "l"(src))
#define CP_COMMIT() asm volatile("cp.async.commit_group;" ::: "memory")
#define CP_WAIT1() asm volatile("cp.async.wait_group 1;" ::: "memory")
#define CP_WAIT0() asm volatile("cp.async.wait_group 0;" ::: "memory")

__device__ __forceinline__ void ldsm_x4(uint32_t* r, uint32_t addr) {
    asm volatile("ldmatrix.sync.aligned.m8n8.x4.shared.b16 {%0,%1,%2,%3}, [%4];"
        : "=r"(r[0]), "=r"(r[1]), "=r"(r[2]), "=r"(r[3]) : "r"(addr));
}
__device__ __forceinline__ void mma16816(float* d, const uint32_t* a, const uint32_t* b) {
    asm volatile("mma.sync.aligned.m16n8k16.row.col.f32.f16.f16.f32 "
        "{%0,%1,%2,%3}, {%4,%5,%6,%7}, {%8,%9}, {%0,%1,%2,%3};"
        : "+f"(d[0]), "+f"(d[1]), "+f"(d[2]), "+f"(d[3])
        : "r"(a[0]), "r"(a[1]), "r"(a[2]), "r"(a[3]), "r"(b[0]), "r"(b[1]));
}

// Block-linear ldmatrix-native layouts (BK=64 fp16 -> 8 x 16B columns per row).
// Each 8x16B matrix is one contiguous 128B block: conflict-free LDSM + coalesced stores.
// A plane: 256 rows (32KB); B plane: 128 rows (16KB).
__device__ __forceinline__ uint32_t blinA(int row, int c16) {
    return (uint32_t)(c16 * 4096 + ((row >> 3) << 7) + ((row & 7) << 4));
}
__device__ __forceinline__ uint32_t blinB(int row, int c16) {
    return (uint32_t)(c16 * 2048 + ((row >> 3) << 7) + ((row & 7) << 4));
}

// Tiles: CTA 256(M) x 128(N) x 64(K); warps 4x2 of 64x64, 1-product.
// Stage: A 32K | B 16K = 48KB; 2 stages = 96KB
#define OFF_B 32768
#define STAGE_B 49152
#define GEMM_SMEM 98304

// Epilogue IDs
#define EPI_QK  0  // dual-source, bias + single fp16, row-major
#define EPI_VT  1  // bias + single fp16, transposed (write V^T)
#define EPI_SC  2  // scale + mask -> fp32
#define EPI_CTX 3  // single fp16, row-major (head-concat via oOff)
#define EPI_OUT 4  // bias -> fp32

// Uniform 1-product GEMM: D = A*B^T (A, B single fp16), BK = 64
template<int EPI>
__global__ void __launch_bounds__(256, 1) gemm1(
    const hf* __restrict__ Ah, const hf* __restrict__ A2h, int lda,
    const hf* __restrict__ Bh, const hf* __restrict__ B2h, int ldb,
    int Ktot,
    const float* __restrict__ bias, const float* __restrict__ bias2,
    const int* __restrict__ mask,
    float* __restrict__ outf,
    hf* __restrict__ oh, int ldo)
{
    extern __shared__ char smem[];
    const uint32_t sb = smem_u32(smem);
    const int tid = threadIdx.x;
    const int wid = tid >> 5;
    const int lane = tid & 31;
    const int z = blockIdx.z;
    const int m0 = blockIdx.y * 256;
    const int n0 = blockIdx.x * 128;

    size_t aOff = 0, bOff = 0, oOff = 0, mOff = 0;
    if (EPI == EPI_QK) {
        const int zz = z & 63;
        if (z >= 64) { Ah = A2h; Bh = B2h; bias = bias2; }
        aOff = (size_t)(zz >> 3) * SLQ * DD;
        bOff = (size_t)(zz & 7) * DD * DD;
        oOff = (size_t)z * SLQ * DD;
    } else if (EPI == EPI_VT) {
        aOff = (size_t)(z >> 3) * SLQ * DD;
        bOff = (size_t)(z & 7) * DD * DD;
        oOff = (size_t)z * DD * SLK;
    } else if (EPI == EPI_SC) {
        aOff = (size_t)z * SLQ * DD;
        bOff = (size_t)z * SLK * DD;
        oOff = (size_t)z * SLQ * SLK;
        mOff = (size_t)(z >> 3) * SLQ * SLK;
    } else if (EPI == EPI_CTX) {
        aOff = (size_t)z * SLQ * SLK;
        bOff = (size_t)z * DD * SLK;
        oOff = (size_t)(z >> 3) * SLQ * HD + (size_t)(z & 7) * DD;
    }

    // ---- loader mapping: 256 threads; c16 = tid&7, row base = tid>>3 (0..31)
    const int c16 = tid & 7;
    const int rb8 = tid >> 3;
    uint32_t dA[8], dB[4];
    #pragma unroll
    for (int i = 0; i < 8; i++) dA[i] = blinA(rb8 + 32 * i, c16);
    #pragma unroll
    for (int i = 0; i < 4; i++) dB[i] = blinB(rb8 + 32 * i, c16);
    const hf* sA = Ah + aOff + (size_t)(m0 + rb8) * lda + c16 * 8;
    const hf* sB = Bh + bOff + (size_t)(n0 + rb8) * ldb + c16 * 8;
    const size_t r32a = (size_t)32 * lda;
    const size_t r32b = (size_t)32 * ldb;

    const int NCH = Ktot >> 6;  // BK = 64

#define LOAD_CHUNK(stg, kt) do { \
    const uint32_t _b = sb + (stg) * STAGE_B; \
    _Pragma("unroll") \
    for (int i = 0; i < 8; i++) CP_ASYNC16(_b + dA[i],         sA + (kt) + (size_t)i * r32a); \
    _Pragma("unroll") \
    for (int i = 0; i < 4; i++) CP_ASYNC16(_b + OFF_B + dB[i], sB + (kt) + (size_t)i * r32b); \
    CP_COMMIT(); } while (0)

    LOAD_CHUNK(0, 0);

    // ---- compute mapping: warp grid 4(M) x 2(N), warp tile 64x64
    const int warpM = wid >> 1;
    const int warpN = wid & 1;
    const int grp = lane >> 3;
    const int l7  = lane & 7;
    const int arowb = warpM * 64 + ((grp & 1) << 3) + l7;   // + mt*16
    const int akc   = grp >> 1;                              // + 2*ks
    const int browb = warpN * 64 + ((grp >> 1) << 3) + l7;  // + p*16
    const int bkc   = grp & 1;                               // + 2*ks

    float acc[4][8][4];
    #pragma unroll
    for (int mt = 0; mt < 4; mt++)
        #pragma unroll
        for (int nt = 0; nt < 8; nt++)
            #pragma unroll
            for (int j = 0; j < 4; j++) acc[mt][nt][j] = 0.f;

    for (int c = 0; c < NCH; c++) {
        if (c + 1 < NCH) {
            LOAD_CHUNK((c + 1) & 1, (size_t)(c + 1) * 64);
            CP_WAIT1();
        } else {
            CP_WAIT0();
        }
        __syncthreads();

        const uint32_t st = sb + (c & 1) * STAGE_B;
        #pragma unroll
        for (int ks = 0; ks < 4; ks++) {
            uint32_t ah[4][4];
            #pragma unroll
            for (int mt = 0; mt < 4; mt++) {
                const uint32_t off = blinA(arowb + mt * 16, 2 * ks + akc);
                ldsm_x4(ah[mt], st + off);
            }
            #pragma unroll
            for (int p = 0; p < 4; p++) {
                uint32_t bh[4];
                const uint32_t off = blinB(browb + p * 16, 2 * ks + bkc);
                ldsm_x4(bh, st + OFF_B + off);
                #pragma unroll
                for (int mt = 0; mt < 4; mt++) {
                    #pragma unroll
                    for (int h = 0; h < 2; h++) {
                        mma16816(acc[mt][p * 2 + h], ah[mt], &bh[h * 2]);
                    }
                }
            }
        }
        __syncthreads();
    }

    // ---------------- epilogue ----------------
    const int r4 = lane >> 2;
    const int c2 = (lane & 3) * 2;
    const int colb = n0 + warpN * 64 + c2;

    #pragma unroll
    for (int mt = 0; mt < 4; mt++) {
        #pragma unroll
        for (int rh = 0; rh < 2; rh++) {
            const int row = m0 + warpM * 64 + mt * 16 + rh * 8 + r4;
            if (EPI == EPI_QK || EPI == EPI_CTX) {
                const size_t rowbase = oOff + (size_t)row * ldo + colb;
                #pragma unroll
                for (int nt = 0; nt < 8; nt++) {
                    const int col = colb + nt * 8;
                    float v0 = acc[mt][nt][rh * 2 + 0];
                    float v1 = acc[mt][nt][rh * 2 + 1];
                    if (EPI == EPI_QK) { v0 += bias[col]; v1 += bias[col + 1]; }
                    hf h0 = __float2half_rn(v0);
                    hf h1 = __float2half_rn(v1);
                    uint32_t ph = (uint32_t)*(unsigned short*)&h0 | ((uint32_t)*(unsigned short*)&h1 << 16);
                    *(uint32_t*)(oh + rowbase + nt * 8) = ph;
                }
            } else if (EPI == EPI_VT) {
                #pragma unroll
                for (int nt = 0; nt < 8; nt++) {
                    const int col = colb + nt * 8;
                    float v0 = acc[mt][nt][rh * 2 + 0] + bias[col];
                    float v1 = acc[mt][nt][rh * 2 + 1] + bias[col + 1];
                    const size_t i0 = oOff + (size_t)col * SLK + row;
                    oh[i0] = __float2half_rn(v0);
                    oh[i0 + SLK] = __float2half_rn(v1);
                }
            } else if (EPI == EPI_SC) {
                const float scale = 0.044194173824159216f;  // 1/sqrt(512)
                const size_t rowbase = oOff + (size_t)row * SLK + colb;
                const int* mp = mask + mOff + (size_t)row * SLK + colb;
                #pragma unroll
                for (int nt = 0; nt < 8; nt++) {
                    int2 mk = *(const int2*)(mp + nt * 8);
                    float2 o;
                    o.x = mk.x ? acc[mt][nt][rh * 2 + 0] * scale : -1e30f;
                    o.y = mk.y ? acc[mt][nt][rh * 2 + 1] * scale : -1e30f;
                    *(float2*)(outf + rowbase + nt * 8) = o;
                }
            } else {  // EPI_OUT
                const size_t rowbase = (size_t)row * ldo + colb;
                #pragma unroll
                for (int nt = 0; nt < 8; nt++) {
                    const int col = colb + nt * 8;
                    float2 o;
                    o.x = acc[mt][nt][rh * 2 + 0] + bias[col];
                    o.y = acc[mt][nt][rh * 2 + 1] + bias[col + 1];
                    *(float2*)(outf + rowbase + nt * 8) = o;
                }
            }
        }
    }
}

// ---------------- fused fp32 -> fp16 conversion (single plane, all tensors) ----------------
__global__ void cvt_all(
    const float* __restrict__ x, const float* __restrict__ st,
    const float* __restrict__ wq, const float* __restrict__ wk,
    const float* __restrict__ wv, const float* __restrict__ wp,
    hf* x1, hf* st1, hf* wq1, hf* wk1, hf* wv1, hf* wp1)
{
    const int which = blockIdx.y;
    const float* s; hf* d; int n4;
    if (which == 0)      { s = x;  d = x1;  n4 = NB*SLQ*DD/4; }
    else if (which == 1) { s = st; d = st1; n4 = NB*SLK*DD/4; }
    else if (which == 2) { s = wq; d = wq1; n4 = NH*DD*DD/4; }
    else if (which == 3) { s = wk; d = wk1; n4 = NH*DD*DD/4; }
    else if (which == 4) { s = wv; d = wv1; n4 = NH*DD*DD/4; }
    else                 { s = wp; d = wp1; n4 = DD*HD/4; }
    int i = blockIdx.x * blockDim.x + threadIdx.x;
    if (i >= n4) return;
    float4 v = ((const float4*)s)[i];
    uint2 vh;
    unsigned short* ph = (unsigned short*)&vh;
    hf a = __float2half_rn(v.x), b = __float2half_rn(v.y);
    hf c = __float2half_rn(v.z), dd = __float2half_rn(v.w);
    ph[0] = *(unsigned short*)&a; ph[1] = *(unsigned short*)&b;
    ph[2] = *(unsigned short*)&c; ph[3] = *(unsigned short*)&dd;
    ((uint2*)d)[i] = vh;
}

// ---------------- softmax over Lk=1024, emit single-plane fp16 ----------------
__global__ void __launch_bounds__(256) softmax_hl()
{
    const size_t row = blockIdx.x;
    const float* p = g_S + row * SLK;
    hf* ph = g_P + row * SLK;
    const int tid = threadIdx.x;
    const int wid = tid >> 5, lane = tid & 31;
    __shared__ float sred[8];

    float4 v = ((const float4*)p)[tid];
    float m = fmaxf(fmaxf(v.x, v.y), fmaxf(v.z, v.w));
    #pragma unroll
    for (int o = 16; o; o >>= 1) m = fmaxf(m, __shfl_xor_sync(0xffffffffu, m, o));
    if (lane == 0) sred[wid] = m;
    __syncthreads();
    float rm = sred[0];
    #pragma unroll
    for (int i = 1; i < 8; i++) rm = fmaxf(rm, sred[i]);
    __syncthreads();

    v.x = __expf(v.x - rm); v.y = __expf(v.y - rm);
    v.z = __expf(v.z - rm); v.w = __expf(v.w - rm);
    float sum = (v.x + v.y) + (v.z + v.w);
    #pragma unroll
    for (int o = 16; o; o >>= 1) sum += __shfl_xor_sync(0xffffffffu, sum, o);
    if (lane == 0) sred[wid] = sum;
    __syncthreads();
    float tot = 0.f;
    #pragma unroll
    for (int i = 0; i < 8; i++) tot += sred[i];
    const float inv = 1.0f / tot;

    uint2 vh;
    unsigned short* qh = (unsigned short*)&vh;
    hf a = __float2half_rn(v.x * inv), b = __float2half_rn(v.y * inv);
    hf c = __float2half_rn(v.z * inv), d = __float2half_rn(v.w * inv);
    qh[0] = *(unsigned short*)&a; qh[1] = *(unsigned short*)&b;
    qh[2] = *(unsigned short*)&c; qh[3] = *(unsigned short*)&d;
    ((uint2*)ph)[tid] = vh;
}

// ---------------- host launch ----------------
template<typename T>
static T* symaddr(const void* sym) {
    void* p = nullptr;
    cudaGetSymbolAddress(&p, sym);
    return (T*)p;
}

extern "C" void kernel_launch(void* const* d_in, const int* in_sizes, int n_in,
                              void* d_out, int out_size)
{
    const float* x      = (const float*)d_in[0];
    const float* states = (const float*)d_in[1];
    const int*   mask   = (const int*)  d_in[2];
    const float* Wq     = (const float*)d_in[3];
    const float* bq     = (const float*)d_in[4];
    const float* Wk     = (const float*)d_in[5];
    const float* bk     = (const float*)d_in[6];
    const float* Wv     = (const float*)d_in[7];
    const float* bv     = (const float*)d_in[8];
    const float* Wp     = (const float*)d_in[9];
    const float* bp     = (const float*)d_in[10];
    float* out = (float*)d_out;

    hf *x1 = symaddr<hf>(g_x);
    hf *st1 = symaddr<hf>(g_st);
    hf *wq1 = symaddr<hf>(g_Wq);
    hf *wk1 = symaddr<hf>(g_Wk);
    hf *wv1 = symaddr<hf>(g_Wv);
    hf *wp1 = symaddr<hf>(g_Wp);
    hf *qk1 = symaddr<hf>(g_QK);
    hf *vt1 = symaddr<hf>(g_VT);
    float *Sf = symaddr<float>(g_S);
    hf *p1 = symaddr<hf>(g_P);
    hf *c1 = symaddr<hf>(g_C);

    cudaFuncSetAttribute((const void*)gemm1<EPI_QK>,  cudaFuncAttributeMaxDynamicSharedMemorySize, GEMM_SMEM);
    cudaFuncSetAttribute((const void*)gemm1<EPI_VT>,  cudaFuncAttributeMaxDynamicSharedMemorySize, GEMM_SMEM);
    cudaFuncSetAttribute((const void*)gemm1<EPI_SC>,  cudaFuncAttributeMaxDynamicSharedMemorySize, GEMM_SMEM);
    cudaFuncSetAttribute((const void*)gemm1<EPI_CTX>, cudaFuncAttributeMaxDynamicSharedMemorySize, GEMM_SMEM);
    cudaFuncSetAttribute((const void*)gemm1<EPI_OUT>, cudaFuncAttributeMaxDynamicSharedMemorySize, GEMM_SMEM);

    // Launch 0: all conversions in one grid (single plane everywhere)
    cvt_all<<<dim3(4096, 6), 256>>>(x, states, Wq, Wk, Wv, Wp,
        x1, st1, wq1, wk1, wv1, wp1);

    // Launch 1: Q (z<64) and K (z>=64) projections, 1-product BK=64
    gemm1<EPI_QK><<<dim3(4, 4, 128), 256, GEMM_SMEM>>>(
        x1, st1, DD, wq1, wk1, DD, DD,
        bq, bk, nullptr, nullptr, qk1, DD);

    // Launch 2: V projection -> V^T
    gemm1<EPI_VT><<<dim3(4, 4, 64), 256, GEMM_SMEM>>>(
        st1, nullptr, DD, wv1, nullptr, DD, DD,
        bv, nullptr, nullptr, nullptr, vt1, SLK);

    // Launch 3: scores = Q K^T * scale, masked
    gemm1<EPI_SC><<<dim3(8, 4, 64), 256, GEMM_SMEM>>>(
        qk1, nullptr, DD,
        qk1 + (size_t)64 * SLQ * DD, nullptr, DD, DD,
        nullptr, nullptr, mask, Sf, nullptr, SLK);

    // Launch 4: softmax -> single-plane fp16 P
    softmax_hl<<<65536, 256>>>();

    // Launch 5 (profiled): ctx = P V
    gemm1<EPI_CTX><<<dim3(4, 4, 64), 256, GEMM_SMEM>>>(
        p1, nullptr, SLK, vt1, nullptr, SLK, SLK,
        nullptr, nullptr, nullptr, nullptr, c1, HD);

    // Launch 6: out = C Wp^T + bp
    gemm1<EPI_OUT><<<dim3(4, 32, 1), 256, GEMM_SMEM>>>(
        c1, nullptr, HD, wp1, nullptr, HD, HD,
        bp, nullptr, nullptr, out, nullptr, DD);
}

// round 15
// speedup vs baseline: 1.8971x; 1.8971x over previous
#include <cuda_runtime.h>
#include <cuda_fp16.h>
#include <cstdint>

// Problem dims
#define NB 8
#define NH 8
#define SLQ 1024
#define SLK 1024
#define DD 512
#define HD 4096

using hf = __half;

// ---------------- device global scratch ----------------
__device__ hf g_x[(size_t)NB*SLQ*DD];
__device__ hf g_st[(size_t)NB*SLK*DD];
__device__ hf g_Wq[(size_t)NH*DD*DD];
__device__ hf g_Wk[(size_t)NH*DD*DD];
__device__ hf g_Wv[(size_t)NH*DD*DD];
__device__ hf g_Wp[(size_t)DD*HD];
__device__ hf g_QK[(size_t)128*SLQ*DD];    // single-plane Q (z<64), K (z>=64)
__device__ hf g_VT[(size_t)64*DD*SLK];
__device__ float g_S[(size_t)64*SLQ*SLK];
__device__ hf g_P[(size_t)64*SLQ*SLK];     // single-plane P
__device__ hf g_C[(size_t)NB*SLQ*HD];      // single-plane ctx

// ---------------- PTX helpers (baseline ISA only) ----------------
__device__ __forceinline__ uint32_t smem_u32(const void* p) {
    uint32_t a;
    asm("{ .reg .u64 t; cvta.to.shared.u64 t, %1; cvt.u32.u64 %0, t; }" : "=r"(a) : "l"(p));
    return a;
}
#define CP_ASYNC16(dst, src) \
    asm volatile("cp.async.cg.shared.global [%0], [%1], 16;" :: "r"(dst), "l"(src))
#define CP_COMMIT() asm volatile("cp.async.commit_group;" ::: "memory")
#define CP_WAIT1() asm volatile("cp.async.wait_group 1;" ::: "memory")
#define CP_WAIT0() asm volatile("cp.async.wait_group 0;" ::: "memory")

__device__ __forceinline__ void ldsm_x4(uint32_t* r, uint32_t addr) {
    asm volatile("ldmatrix.sync.aligned.m8n8.x4.shared.b16 {%0,%1,%2,%3}, [%4];"
        : "=r"(r[0]), "=r"(r[1]), "=r"(r[2]), "=r"(r[3]) : "r"(addr));
}
__device__ __forceinline__ void mma16816(float* d, const uint32_t* a, const uint32_t* b) {
    asm volatile("mma.sync.aligned.m16n8k16.row.col.f32.f16.f16.f32 "
        "{%0,%1,%2,%3}, {%4,%5,%6,%7}, {%8,%9}, {%0,%1,%2,%3};"
        : "+f"(d[0]), "+f"(d[1]), "+f"(d[2]), "+f"(d[3])
        : "r"(a[0]), "r"(a[1]), "r"(a[2]), "r"(a[3]), "r"(b[0]), "r"(b[1]));
}

// 64B-row swizzle: slot' = chunk ^ ((row>>1)&3), conflict-free for ldmatrix groups
__device__ __forceinline__ uint32_t swzoff(int row, int chunk) {
    return (uint32_t)row * 64u + (uint32_t)((chunk ^ ((row >> 1) & 3)) << 4);
}

// Tiles: CTA 128(M) x 128(N) x 32(K); 8 warps in 2(M) x 4(N), warp tile 64x32.
// acc = 64 regs/thread -> __launch_bounds__(256,2) -> 2 CTAs/SM, 16 warps/SM.
// SMEM stage: A 8K | B 8K = 16KB; 2 stages = 32KB/CTA (64KB/SM at 2 CTAs)
#define OFF_B 8192
#define STAGE_B 16384
#define GEMM_SMEM 32768

// Epilogue IDs
#define EPI_QK  0  // dual-source, bias + single fp16, row-major
#define EPI_VT  1  // bias + single fp16, transposed (write V^T)
#define EPI_SC  2  // scale + mask -> fp32
#define EPI_CTX 3  // single fp16, row-major (head-concat via oOff)
#define EPI_OUT 4  // bias -> fp32

// Uniform 1-product GEMM: D = A*B^T (A, B single fp16), BK = 32
template<int EPI>
__global__ void __launch_bounds__(256, 2) gemm1(
    const hf* __restrict__ Ah, const hf* __restrict__ A2h, int lda,
    const hf* __restrict__ Bh, const hf* __restrict__ B2h, int ldb,
    int Ktot,
    const float* __restrict__ bias, const float* __restrict__ bias2,
    const int* __restrict__ mask,
    float* __restrict__ outf,
    hf* __restrict__ oh, int ldo)
{
    extern __shared__ char smem[];
    const uint32_t sb = smem_u32(smem);
    const int tid = threadIdx.x;
    const int wid = tid >> 5;
    const int lane = tid & 31;
    const int z = blockIdx.z;
    const int m0 = blockIdx.y * 128;
    const int n0 = blockIdx.x * 128;

    size_t aOff = 0, bOff = 0, oOff = 0, mOff = 0;
    if (EPI == EPI_QK) {
        const int zz = z & 63;
        if (z >= 64) { Ah = A2h; Bh = B2h; bias = bias2; }
        aOff = (size_t)(zz >> 3) * SLQ * DD;
        bOff = (size_t)(zz & 7) * DD * DD;
        oOff = (size_t)z * SLQ * DD;
    } else if (EPI == EPI_VT) {
        aOff = (size_t)(z >> 3) * SLQ * DD;
        bOff = (size_t)(z & 7) * DD * DD;
        oOff = (size_t)z * DD * SLK;
    } else if (EPI == EPI_SC) {
        aOff = (size_t)z * SLQ * DD;
        bOff = (size_t)z * SLK * DD;
        oOff = (size_t)z * SLQ * SLK;
        mOff = (size_t)(z >> 3) * SLQ * SLK;
    } else if (EPI == EPI_CTX) {
        aOff = (size_t)z * SLQ * SLK;
        bOff = (size_t)z * DD * SLK;
        oOff = (size_t)(z >> 3) * SLQ * HD + (size_t)(z & 7) * DD;
    }

    // ---- loader mapping: 256 threads; A: 2 row-passes, B: 2 row-passes
    const int lc = tid & 3;     // 16B k-chunk (0..3)
    const int lr = tid >> 2;    // row 0..63
    const uint32_t s0 = swzoff(lr, lc);
    const uint32_t s1 = swzoff(lr + 64, lc);
    const hf* sA = Ah + aOff + (size_t)(m0 + lr) * lda + lc * 8;
    const hf* sB = Bh + bOff + (size_t)(n0 + lr) * ldb + lc * 8;
    const size_t r64a = (size_t)64 * lda;
    const size_t r64b = (size_t)64 * ldb;

    const int NCH = Ktot >> 5;  // BK = 32

#define LOAD_CHUNK(stg, kt) do { \
    const uint32_t _b = sb + (stg) * STAGE_B; \
    CP_ASYNC16(_b + s0,         sA + (kt)); \
    CP_ASYNC16(_b + s1,         sA + (kt) + r64a); \
    CP_ASYNC16(_b + OFF_B + s0, sB + (kt)); \
    CP_ASYNC16(_b + OFF_B + s1, sB + (kt) + r64b); \
    CP_COMMIT(); } while (0)

    LOAD_CHUNK(0, 0);

    // ---- compute mapping: warp grid 2(M) x 4(N), warp tile 64x32
    const int warpM = wid >> 2;      // 0..1
    const int warpN = wid & 3;       // 0..3
    const int grp = lane >> 3;
    const int l7  = lane & 7;
    const int arowb = warpM * 64 + ((grp & 1) << 3) + l7;   // + mt*16
    const int akc   = grp >> 1;                              // + ks*2
    const int browb = warpN * 32 + ((grp >> 1) << 3) + l7;  // + p*16
    const int bkc   = grp & 1;                               // + ks*2

    float acc[4][4][4];
    #pragma unroll
    for (int mt = 0; mt < 4; mt++)
        #pragma unroll
        for (int nt = 0; nt < 4; nt++)
            #pragma unroll
            for (int j = 0; j < 4; j++) acc[mt][nt][j] = 0.f;

    for (int c = 0; c < NCH; c++) {
        if (c + 1 < NCH) {
            LOAD_CHUNK((c + 1) & 1, (size_t)(c + 1) * 32);
            CP_WAIT1();
        } else {
            CP_WAIT0();
        }
        __syncthreads();

        const uint32_t st = sb + (c & 1) * STAGE_B;
        #pragma unroll
        for (int ks = 0; ks < 2; ks++) {
            uint32_t ah[4][4];
            #pragma unroll
            for (int mt = 0; mt < 4; mt++) {
                const uint32_t off = swzoff(arowb + mt * 16, akc + ks * 2);
                ldsm_x4(ah[mt], st + off);
            }
            #pragma unroll
            for (int p = 0; p < 2; p++) {
                uint32_t bh[4];
                const uint32_t off = swzoff(browb + p * 16, bkc + ks * 2);
                ldsm_x4(bh, st + OFF_B + off);
                #pragma unroll
                for (int mt = 0; mt < 4; mt++) {
                    #pragma unroll
                    for (int h = 0; h < 2; h++) {
                        mma16816(acc[mt][p * 2 + h], ah[mt], &bh[h * 2]);
                    }
                }
            }
        }
        __syncthreads();
    }

    // ---------------- epilogue ----------------
    const int r4 = lane >> 2;
    const int c2 = (lane & 3) * 2;
    const int colb = n0 + warpN * 32 + c2;

    #pragma unroll
    for (int mt = 0; mt < 4; mt++) {
        #pragma unroll
        for (int rh = 0; rh < 2; rh++) {
            const int row = m0 + warpM * 64 + mt * 16 + rh * 8 + r4;
            if (EPI == EPI_QK || EPI == EPI_CTX) {
                const size_t rowbase = oOff + (size_t)row * ldo + colb;
                #pragma unroll
                for (int nt = 0; nt < 4; nt++) {
                    const int col = colb + nt * 8;
                    float v0 = acc[mt][nt][rh * 2 + 0];
                    float v1 = acc[mt][nt][rh * 2 + 1];
                    if (EPI == EPI_QK) { v0 += bias[col]; v1 += bias[col + 1]; }
                    hf h0 = __float2half_rn(v0);
                    hf h1 = __float2half_rn(v1);
                    uint32_t ph = (uint32_t)*(unsigned short*)&h0 | ((uint32_t)*(unsigned short*)&h1 << 16);
                    *(uint32_t*)(oh + rowbase + nt * 8) = ph;
                }
            } else if (EPI == EPI_VT) {
                #pragma unroll
                for (int nt = 0; nt < 4; nt++) {
                    const int col = colb + nt * 8;
                    float v0 = acc[mt][nt][rh * 2 + 0] + bias[col];
                    float v1 = acc[mt][nt][rh * 2 + 1] + bias[col + 1];
                    const size_t i0 = oOff + (size_t)col * SLK + row;
                    oh[i0] = __float2half_rn(v0);
                    oh[i0 + SLK] = __float2half_rn(v1);
                }
            } else if (EPI == EPI_SC) {
                const float scale = 0.044194173824159216f;  // 1/sqrt(512)
                const size_t rowbase = oOff + (size_t)row * SLK + colb;
                const int* mp = mask + mOff + (size_t)row * SLK + colb;
                #pragma unroll
                for (int nt = 0; nt < 4; nt++) {
                    int2 mk = *(const int2*)(mp + nt * 8);
                    float2 o;
                    o.x = mk.x ? acc[mt][nt][rh * 2 + 0] * scale : -1e30f;
                    o.y = mk.y ? acc[mt][nt][rh * 2 + 1] * scale : -1e30f;
                    *(float2*)(outf + rowbase + nt * 8) = o;
                }
            } else {  // EPI_OUT
                const size_t rowbase = (size_t)row * ldo + colb;
                #pragma unroll
                for (int nt = 0; nt < 4; nt++) {
                    const int col = colb + nt * 8;
                    float2 o;
                    o.x = acc[mt][nt][rh * 2 + 0] + bias[col];
                    o.y = acc[mt][nt][rh * 2 + 1] + bias[col + 1];
                    *(float2*)(outf + rowbase + nt * 8) = o;
                }
            }
        }
    }
}

// ---------------- fused fp32 -> fp16 conversion (single plane, all tensors) ----------------
__global__ void cvt_all(
    const float* __restrict__ x, const float* __restrict__ st,
    const float* __restrict__ wq, const float* __restrict__ wk,
    const float* __restrict__ wv, const float* __restrict__ wp,
    hf* x1, hf* st1, hf* wq1, hf* wk1, hf* wv1, hf* wp1)
{
    const int which = blockIdx.y;
    const float* s; hf* d; int n4;
    if (which == 0)      { s = x;  d = x1;  n4 = NB*SLQ*DD/4; }
    else if (which == 1) { s = st; d = st1; n4 = NB*SLK*DD/4; }
    else if (which == 2) { s = wq; d = wq1; n4 = NH*DD*DD/4; }
    else if (which == 3) { s = wk; d = wk1; n4 = NH*DD*DD/4; }
    else if (which == 4) { s = wv; d = wv1; n4 = NH*DD*DD/4; }
    else                 { s = wp; d = wp1; n4 = DD*HD/4; }
    int i = blockIdx.x * blockDim.x + threadIdx.x;
    if (i >= n4) return;
    float4 v = ((const float4*)s)[i];
    uint2 vh;
    unsigned short* ph = (unsigned short*)&vh;
    hf a = __float2half_rn(v.x), b = __float2half_rn(v.y);
    hf c = __float2half_rn(v.z), dd = __float2half_rn(v.w);
    ph[0] = *(unsigned short*)&a; ph[1] = *(unsigned short*)&b;
    ph[2] = *(unsigned short*)&c; ph[3] = *(unsigned short*)&dd;
    ((uint2*)d)[i] = vh;
}

// ---------------- softmax over Lk=1024, emit single-plane fp16 ----------------
__global__ void __launch_bounds__(256) softmax_hl()
{
    const size_t row = blockIdx.x;
    const float* p = g_S + row * SLK;
    hf* ph = g_P + row * SLK;
    const int tid = threadIdx.x;
    const int wid = tid >> 5, lane = tid & 31;
    __shared__ float sred[8];

    float4 v = ((const float4*)p)[tid];
    float m = fmaxf(fmaxf(v.x, v.y), fmaxf(v.z, v.w));
    #pragma unroll
    for (int o = 16; o; o >>= 1) m = fmaxf(m, __shfl_xor_sync(0xffffffffu, m, o));
    if (lane == 0) sred[wid] = m;
    __syncthreads();
    float rm = sred[0];
    #pragma unroll
    for (int i = 1; i < 8; i++) rm = fmaxf(rm, sred[i]);
    __syncthreads();

    v.x = __expf(v.x - rm); v.y = __expf(v.y - rm);
    v.z = __expf(v.z - rm); v.w = __expf(v.w - rm);
    float sum = (v.x + v.y) + (v.z + v.w);
    #pragma unroll
    for (int o = 16; o; o >>= 1) sum += __shfl_xor_sync(0xffffffffu, sum, o);
    if (lane == 0) sred[wid] = sum;
    __syncthreads();
    float tot = 0.f;
    #pragma unroll
    for (int i = 0; i < 8; i++) tot += sred[i];
    const float inv = 1.0f / tot;

    uint2 vh;
    unsigned short* qh = (unsigned short*)&vh;
    hf a = __float2half_rn(v.x * inv), b = __float2half_rn(v.y * inv);
    hf c = __float2half_rn(v.z * inv), d = __float2half_rn(v.w * inv);
    qh[0] = *(unsigned short*)&a; qh[1] = *(unsigned short*)&b;
    qh[2] = *(unsigned short*)&c; qh[3] = *(unsigned short*)&d;
    ((uint2*)ph)[tid] = vh;
}

// ---------------- host launch ----------------
template<typename T>
static T* symaddr(const void* sym) {
    void* p = nullptr;
    cudaGetSymbolAddress(&p, sym);
    return (T*)p;
}

extern "C" void kernel_launch(void* const* d_in, const int* in_sizes, int n_in,
                              void* d_out, int out_size)
{
    const float* x      = (const float*)d_in[0];
    const float* states = (const float*)d_in[1];
    const int*   mask   = (const int*)  d_in[2];
    const float* Wq     = (const float*)d_in[3];
    const float* bq     = (const float*)d_in[4];
    const float* Wk     = (const float*)d_in[5];
    const float* bk     = (const float*)d_in[6];
    const float* Wv     = (const float*)d_in[7];
    const float* bv     = (const float*)d_in[8];
    const float* Wp     = (const float*)d_in[9];
    const float* bp     = (const float*)d_in[10];
    float* out = (float*)d_out;

    hf *x1 = symaddr<hf>(g_x);
    hf *st1 = symaddr<hf>(g_st);
    hf *wq1 = symaddr<hf>(g_Wq);
    hf *wk1 = symaddr<hf>(g_Wk);
    hf *wv1 = symaddr<hf>(g_Wv);
    hf *wp1 = symaddr<hf>(g_Wp);
    hf *qk1 = symaddr<hf>(g_QK);
    hf *vt1 = symaddr<hf>(g_VT);
    float *Sf = symaddr<float>(g_S);
    hf *p1 = symaddr<hf>(g_P);
    hf *c1 = symaddr<hf>(g_C);

    cudaFuncSetAttribute((const void*)gemm1<EPI_QK>,  cudaFuncAttributeMaxDynamicSharedMemorySize, GEMM_SMEM);
    cudaFuncSetAttribute((const void*)gemm1<EPI_VT>,  cudaFuncAttributeMaxDynamicSharedMemorySize, GEMM_SMEM);
    cudaFuncSetAttribute((const void*)gemm1<EPI_SC>,  cudaFuncAttributeMaxDynamicSharedMemorySize, GEMM_SMEM);
    cudaFuncSetAttribute((const void*)gemm1<EPI_CTX>, cudaFuncAttributeMaxDynamicSharedMemorySize, GEMM_SMEM);
    cudaFuncSetAttribute((const void*)gemm1<EPI_OUT>, cudaFuncAttributeMaxDynamicSharedMemorySize, GEMM_SMEM);

    // Launch 0: all conversions in one grid (single plane everywhere)
    cvt_all<<<dim3(4096, 6), 256>>>(x, states, Wq, Wk, Wv, Wp,
        x1, st1, wq1, wk1, wv1, wp1);

    // Launch 1: Q (z<64) and K (z>=64) projections (M=1024/128=8, N=512/128=4)
    gemm1<EPI_QK><<<dim3(4, 8, 128), 256, GEMM_SMEM>>>(
        x1, st1, DD, wq1, wk1, DD, DD,
        bq, bk, nullptr, nullptr, qk1, DD);

    // Launch 2: V projection -> V^T
    gemm1<EPI_VT><<<dim3(4, 8, 64), 256, GEMM_SMEM>>>(
        st1, nullptr, DD, wv1, nullptr, DD, DD,
        bv, nullptr, nullptr, nullptr, vt1, SLK);

    // Launch 3: scores = Q K^T * scale, masked (M=8 tiles, N=8 tiles)
    gemm1<EPI_SC><<<dim3(8, 8, 64), 256, GEMM_SMEM>>>(
        qk1, nullptr, DD,
        qk1 + (size_t)64 * SLQ * DD, nullptr, DD, DD,
        nullptr, nullptr, mask, Sf, nullptr, SLK);

    // Launch 4: softmax -> single-plane fp16 P
    softmax_hl<<<65536, 256>>>();

    // Launch 5 (profiled): ctx = P V
    gemm1<EPI_CTX><<<dim3(4, 8, 64), 256, GEMM_SMEM>>>(
        p1, nullptr, SLK, vt1, nullptr, SLK, SLK,
        nullptr, nullptr, nullptr, nullptr, c1, HD);

    // Launch 6: out = C Wp^T + bp (M=8192/128=64, N=4)
    gemm1<EPI_OUT><<<dim3(4, 64, 1), 256, GEMM_SMEM>>>(
        c1, nullptr, HD, wp1, nullptr, HD, HD,
        bp, nullptr, nullptr, out, nullptr, DD);
}

// round 16
// speedup vs baseline: 1.9049x; 1.0041x over previous
#include <cuda_runtime.h>
#include <cuda_fp16.h>
#include <cstdint>

// Problem dims
#define NB 8
#define NH 8
#define SLQ 1024
#define SLK 1024
#define DD 512
#define HD 4096

using hf = __half;

// ---------------- device global scratch ----------------
__device__ hf g_x[(size_t)NB*SLQ*DD];
__device__ hf g_st[(size_t)NB*SLK*DD];
__device__ hf g_Wq[(size_t)NH*DD*DD];
__device__ hf g_Wk[(size_t)NH*DD*DD];
__device__ hf g_Wv[(size_t)NH*DD*DD];
__device__ hf g_Wp[(size_t)DD*HD];
__device__ hf g_QK[(size_t)128*SLQ*DD];    // single-plane Q (z<64), K (z>=64)
__device__ hf g_VT[(size_t)64*DD*SLK];
__device__ float g_S[(size_t)64*SLQ*SLK];
__device__ hf g_P[(size_t)64*SLQ*SLK];     // single-plane P
__device__ hf g_C[(size_t)NB*SLQ*HD];      // single-plane ctx

// ---------------- PTX helpers (baseline ISA only) ----------------
__device__ __forceinline__ uint32_t smem_u32(const void* p) {
    uint32_t a;
    asm("{ .reg .u64 t; cvta.to.shared.u64 t, %1; cvt.u32.u64 %0, t; }" : "=r"(a) : "l"(p));
    return a;
}
#define CP_ASYNC16(dst, src) \
    asm volatile("cp.async.cg.shared.global [%0], [%1], 16;" :: "r"(dst), "l"(src))
#define CP_COMMIT() asm volatile("cp.async.commit_group;" ::: "memory")
#define CP_WAIT1() asm volatile("cp.async.wait_group 1;" ::: "memory")
#define CP_WAIT0() asm volatile("cp.async.wait_group 0;" ::: "memory")

__device__ __forceinline__ void ldsm_x4(uint32_t* r, uint32_t addr) {
    asm volatile("ldmatrix.sync.aligned.m8n8.x4.shared.b16 {%0,%1,%2,%3}, [%4];"
        : "=r"(r[0]), "=r"(r[1]), "=r"(r[2]), "=r"(r[3]) : "r"(addr));
}
__device__ __forceinline__ void mma16816(float* d, const uint32_t* a, const uint32_t* b) {
    asm volatile("mma.sync.aligned.m16n8k16.row.col.f32.f16.f16.f32 "
        "{%0,%1,%2,%3}, {%4,%5,%6,%7}, {%8,%9}, {%0,%1,%2,%3};"
        : "+f"(d[0]), "+f"(d[1]), "+f"(d[2]), "+f"(d[3])
        : "r"(a[0]), "r"(a[1]), "r"(a[2]), "r"(a[3]), "r"(b[0]), "r"(b[1]));
}

// 64B-row swizzle: slot' = chunk ^ ((row>>1)&3), conflict-free for ldmatrix groups
__device__ __forceinline__ uint32_t swzoff(int row, int chunk) {
    return (uint32_t)row * 64u + (uint32_t)((chunk ^ ((row >> 1) & 3)) << 4);
}

// Tiles: CTA 128(M) x 128(N) x 32(K); 4 warps in 2(M) x 2(N), warp tile 64x64.
// __launch_bounds__(128,3) -> <=170 regs -> 3 CTAs/SM, 12 warps/SM.
// LDSM traffic/chunk: (warpsN+warpsM) x 8KB = 32KB read + 16KB store (-33% vs 64x32).
// SMEM stage: A 8K | B 8K = 16KB; 2 stages = 32KB/CTA (96KB/SM at 3 CTAs)
#define OFF_B 8192
#define STAGE_B 16384
#define GEMM_SMEM 32768

// Epilogue IDs
#define EPI_QK  0  // dual-source, bias + single fp16, row-major
#define EPI_VT  1  // bias + single fp16, transposed (write V^T)
#define EPI_SC  2  // scale + mask -> fp32
#define EPI_CTX 3  // single fp16, row-major (head-concat via oOff)
#define EPI_OUT 4  // bias -> fp32

// Uniform 1-product GEMM: D = A*B^T (A, B single fp16), BK = 32
template<int EPI>
__global__ void __launch_bounds__(128, 3) gemm1(
    const hf* __restrict__ Ah, const hf* __restrict__ A2h, int lda,
    const hf* __restrict__ Bh, const hf* __restrict__ B2h, int ldb,
    int Ktot,
    const float* __restrict__ bias, const float* __restrict__ bias2,
    const int* __restrict__ mask,
    float* __restrict__ outf,
    hf* __restrict__ oh, int ldo)
{
    extern __shared__ char smem[];
    const uint32_t sb = smem_u32(smem);
    const int tid = threadIdx.x;
    const int wid = tid >> 5;
    const int lane = tid & 31;
    const int z = blockIdx.z;
    const int m0 = blockIdx.y * 128;
    const int n0 = blockIdx.x * 128;

    size_t aOff = 0, bOff = 0, oOff = 0, mOff = 0;
    if (EPI == EPI_QK) {
        const int zz = z & 63;
        if (z >= 64) { Ah = A2h; Bh = B2h; bias = bias2; }
        aOff = (size_t)(zz >> 3) * SLQ * DD;
        bOff = (size_t)(zz & 7) * DD * DD;
        oOff = (size_t)z * SLQ * DD;
    } else if (EPI == EPI_VT) {
        aOff = (size_t)(z >> 3) * SLQ * DD;
        bOff = (size_t)(z & 7) * DD * DD;
        oOff = (size_t)z * DD * SLK;
    } else if (EPI == EPI_SC) {
        aOff = (size_t)z * SLQ * DD;
        bOff = (size_t)z * SLK * DD;
        oOff = (size_t)z * SLQ * SLK;
        mOff = (size_t)(z >> 3) * SLQ * SLK;
    } else if (EPI == EPI_CTX) {
        aOff = (size_t)z * SLQ * SLK;
        bOff = (size_t)z * DD * SLK;
        oOff = (size_t)(z >> 3) * SLQ * HD + (size_t)(z & 7) * DD;
    }

    // ---- loader mapping: 128 threads; each: 4 A-chunks + 4 B-chunks (16B each)
    const int lc = tid & 3;     // 16B k-chunk (0..3)
    const int lr = tid >> 2;    // row 0..31 (rows lr + 32i)
    uint32_t soff[4];
    #pragma unroll
    for (int i = 0; i < 4; i++)
        soff[i] = swzoff(lr + 32 * i, lc);
    const hf* sA = Ah + aOff + (size_t)(m0 + lr) * lda + lc * 8;
    const hf* sB = Bh + bOff + (size_t)(n0 + lr) * ldb + lc * 8;
    const size_t r32a = (size_t)32 * lda;
    const size_t r32b = (size_t)32 * ldb;

    const int NCH = Ktot >> 5;  // BK = 32

#define LOAD_CHUNK(stg, kt) do { \
    const uint32_t _b = sb + (stg) * STAGE_B; \
    _Pragma("unroll") \
    for (int i = 0; i < 4; i++) CP_ASYNC16(_b + soff[i],         sA + (kt) + (size_t)i * r32a); \
    _Pragma("unroll") \
    for (int i = 0; i < 4; i++) CP_ASYNC16(_b + OFF_B + soff[i], sB + (kt) + (size_t)i * r32b); \
    CP_COMMIT(); } while (0)

    LOAD_CHUNK(0, 0);

    // ---- compute mapping: warp grid 2(M) x 2(N), warp tile 64x64
    const int warpM = wid >> 1;      // 0..1
    const int warpN = wid & 1;       // 0..1
    const int grp = lane >> 3;
    const int l7  = lane & 7;
    const int arowb = warpM * 64 + ((grp & 1) << 3) + l7;   // + mt*16
    const int akc   = grp >> 1;                              // + ks*2
    const int browb = warpN * 64 + ((grp >> 1) << 3) + l7;  // + p*16
    const int bkc   = grp & 1;                               // + ks*2

    float acc[4][8][4];
    #pragma unroll
    for (int mt = 0; mt < 4; mt++)
        #pragma unroll
        for (int nt = 0; nt < 8; nt++)
            #pragma unroll
            for (int j = 0; j < 4; j++) acc[mt][nt][j] = 0.f;

    for (int c = 0; c < NCH; c++) {
        if (c + 1 < NCH) {
            LOAD_CHUNK((c + 1) & 1, (size_t)(c + 1) * 32);
            CP_WAIT1();
        } else {
            CP_WAIT0();
        }
        __syncthreads();

        const uint32_t st = sb + (c & 1) * STAGE_B;
        #pragma unroll
        for (int ks = 0; ks < 2; ks++) {
            uint32_t ah[4][4];
            #pragma unroll
            for (int mt = 0; mt < 4; mt++) {
                const uint32_t off = swzoff(arowb + mt * 16, akc + ks * 2);
                ldsm_x4(ah[mt], st + off);
            }
            #pragma unroll
            for (int p = 0; p < 4; p++) {
                uint32_t bh[4];
                const uint32_t off = swzoff(browb + p * 16, bkc + ks * 2);
                ldsm_x4(bh, st + OFF_B + off);
                #pragma unroll
                for (int mt = 0; mt < 4; mt++) {
                    #pragma unroll
                    for (int h = 0; h < 2; h++) {
                        mma16816(acc[mt][p * 2 + h], ah[mt], &bh[h * 2]);
                    }
                }
            }
        }
        __syncthreads();
    }

    // ---------------- epilogue ----------------
    const int r4 = lane >> 2;
    const int c2 = (lane & 3) * 2;
    const int colb = n0 + warpN * 64 + c2;

    #pragma unroll
    for (int mt = 0; mt < 4; mt++) {
        #pragma unroll
        for (int rh = 0; rh < 2; rh++) {
            const int row = m0 + warpM * 64 + mt * 16 + rh * 8 + r4;
            if (EPI == EPI_QK || EPI == EPI_CTX) {
                const size_t rowbase = oOff + (size_t)row * ldo + colb;
                #pragma unroll
                for (int nt = 0; nt < 8; nt++) {
                    const int col = colb + nt * 8;
                    float v0 = acc[mt][nt][rh * 2 + 0];
                    float v1 = acc[mt][nt][rh * 2 + 1];
                    if (EPI == EPI_QK) { v0 += bias[col]; v1 += bias[col + 1]; }
                    hf h0 = __float2half_rn(v0);
                    hf h1 = __float2half_rn(v1);
                    uint32_t ph = (uint32_t)*(unsigned short*)&h0 | ((uint32_t)*(unsigned short*)&h1 << 16);
                    *(uint32_t*)(oh + rowbase + nt * 8) = ph;
                }
            } else if (EPI == EPI_VT) {
                #pragma unroll
                for (int nt = 0; nt < 8; nt++) {
                    const int col = colb + nt * 8;
                    float v0 = acc[mt][nt][rh * 2 + 0] + bias[col];
                    float v1 = acc[mt][nt][rh * 2 + 1] + bias[col + 1];
                    const size_t i0 = oOff + (size_t)col * SLK + row;
                    oh[i0] = __float2half_rn(v0);
                    oh[i0 + SLK] = __float2half_rn(v1);
                }
            } else if (EPI == EPI_SC) {
                const float scale = 0.044194173824159216f;  // 1/sqrt(512)
                const size_t rowbase = oOff + (size_t)row * SLK + colb;
                const int* mp = mask + mOff + (size_t)row * SLK + colb;
                #pragma unroll
                for (int nt = 0; nt < 8; nt++) {
                    int2 mk = *(const int2*)(mp + nt * 8);
                    float2 o;
                    o.x = mk.x ? acc[mt][nt][rh * 2 + 0] * scale : -1e30f;
                    o.y = mk.y ? acc[mt][nt][rh * 2 + 1] * scale : -1e30f;
                    *(float2*)(outf + rowbase + nt * 8) = o;
                }
            } else {  // EPI_OUT
                const size_t rowbase = (size_t)row * ldo + colb;
                #pragma unroll
                for (int nt = 0; nt < 8; nt++) {
                    const int col = colb + nt * 8;
                    float2 o;
                    o.x = acc[mt][nt][rh * 2 + 0] + bias[col];
                    o.y = acc[mt][nt][rh * 2 + 1] + bias[col + 1];
                    *(float2*)(outf + rowbase + nt * 8) = o;
                }
            }
        }
    }
}

// ---------------- fused fp32 -> fp16 conversion (single plane, all tensors) ----------------
__global__ void cvt_all(
    const float* __restrict__ x, const float* __restrict__ st,
    const float* __restrict__ wq, const float* __restrict__ wk,
    const float* __restrict__ wv, const float* __restrict__ wp,
    hf* x1, hf* st1, hf* wq1, hf* wk1, hf* wv1, hf* wp1)
{
    const int which = blockIdx.y;
    const float* s; hf* d; int n4;
    if (which == 0)      { s = x;  d = x1;  n4 = NB*SLQ*DD/4; }
    else if (which == 1) { s = st; d = st1; n4 = NB*SLK*DD/4; }
    else if (which == 2) { s = wq; d = wq1; n4 = NH*DD*DD/4; }
    else if (which == 3) { s = wk; d = wk1; n4 = NH*DD*DD/4; }
    else if (which == 4) { s = wv; d = wv1; n4 = NH*DD*DD/4; }
    else                 { s = wp; d = wp1; n4 = DD*HD/4; }
    int i = blockIdx.x * blockDim.x + threadIdx.x;
    if (i >= n4) return;
    float4 v = ((const float4*)s)[i];
    uint2 vh;
    unsigned short* ph = (unsigned short*)&vh;
    hf a = __float2half_rn(v.x), b = __float2half_rn(v.y);
    hf c = __float2half_rn(v.z), dd = __float2half_rn(v.w);
    ph[0] = *(unsigned short*)&a; ph[1] = *(unsigned short*)&b;
    ph[2] = *(unsigned short*)&c; ph[3] = *(unsigned short*)&dd;
    ((uint2*)d)[i] = vh;
}

// ---------------- softmax over Lk=1024, emit single-plane fp16 ----------------
__global__ void __launch_bounds__(256) softmax_hl()
{
    const size_t row = blockIdx.x;
    const float* p = g_S + row * SLK;
    hf* ph = g_P + row * SLK;
    const int tid = threadIdx.x;
    const int wid = tid >> 5, lane = tid & 31;
    __shared__ float sred[8];

    float4 v = ((const float4*)p)[tid];
    float m = fmaxf(fmaxf(v.x, v.y), fmaxf(v.z, v.w));
    #pragma unroll
    for (int o = 16; o; o >>= 1) m = fmaxf(m, __shfl_xor_sync(0xffffffffu, m, o));
    if (lane == 0) sred[wid] = m;
    __syncthreads();
    float rm = sred[0];
    #pragma unroll
    for (int i = 1; i < 8; i++) rm = fmaxf(rm, sred[i]);
    __syncthreads();

    v.x = __expf(v.x - rm); v.y = __expf(v.y - rm);
    v.z = __expf(v.z - rm); v.w = __expf(v.w - rm);
    float sum = (v.x + v.y) + (v.z + v.w);
    #pragma unroll
    for (int o = 16; o; o >>= 1) sum += __shfl_xor_sync(0xffffffffu, sum, o);
    if (lane == 0) sred[wid] = sum;
    __syncthreads();
    float tot = 0.f;
    #pragma unroll
    for (int i = 0; i < 8; i++) tot += sred[i];
    const float inv = 1.0f / tot;

    uint2 vh;
    unsigned short* qh = (unsigned short*)&vh;
    hf a = __float2half_rn(v.x * inv), b = __float2half_rn(v.y * inv);
    hf c = __float2half_rn(v.z * inv), d = __float2half_rn(v.w * inv);
    qh[0] = *(unsigned short*)&a; qh[1] = *(unsigned short*)&b;
    qh[2] = *(unsigned short*)&c; qh[3] = *(unsigned short*)&d;
    ((uint2*)ph)[tid] = vh;
}

// ---------------- host launch ----------------
template<typename T>
static T* symaddr(const void* sym) {
    void* p = nullptr;
    cudaGetSymbolAddress(&p, sym);
    return (T*)p;
}

extern "C" void kernel_launch(void* const* d_in, const int* in_sizes, int n_in,
                              void* d_out, int out_size)
{
    const float* x      = (const float*)d_in[0];
    const float* states = (const float*)d_in[1];
    const int*   mask   = (const int*)  d_in[2];
    const float* Wq     = (const float*)d_in[3];
    const float* bq     = (const float*)d_in[4];
    const float* Wk     = (const float*)d_in[5];
    const float* bk     = (const float*)d_in[6];
    const float* Wv     = (const float*)d_in[7];
    const float* bv     = (const float*)d_in[8];
    const float* Wp     = (const float*)d_in[9];
    const float* bp     = (const float*)d_in[10];
    float* out = (float*)d_out;

    hf *x1 = symaddr<hf>(g_x);
    hf *st1 = symaddr<hf>(g_st);
    hf *wq1 = symaddr<hf>(g_Wq);
    hf *wk1 = symaddr<hf>(g_Wk);
    hf *wv1 = symaddr<hf>(g_Wv);
    hf *wp1 = symaddr<hf>(g_Wp);
    hf *qk1 = symaddr<hf>(g_QK);
    hf *vt1 = symaddr<hf>(g_VT);
    float *Sf = symaddr<float>(g_S);
    hf *p1 = symaddr<hf>(g_P);
    hf *c1 = symaddr<hf>(g_C);

    cudaFuncSetAttribute((const void*)gemm1<EPI_QK>,  cudaFuncAttributeMaxDynamicSharedMemorySize, GEMM_SMEM);
    cudaFuncSetAttribute((const void*)gemm1<EPI_VT>,  cudaFuncAttributeMaxDynamicSharedMemorySize, GEMM_SMEM);
    cudaFuncSetAttribute((const void*)gemm1<EPI_SC>,  cudaFuncAttributeMaxDynamicSharedMemorySize, GEMM_SMEM);
    cudaFuncSetAttribute((const void*)gemm1<EPI_CTX>, cudaFuncAttributeMaxDynamicSharedMemorySize, GEMM_SMEM);
    cudaFuncSetAttribute((const void*)gemm1<EPI_OUT>, cudaFuncAttributeMaxDynamicSharedMemorySize, GEMM_SMEM);

    // Launch 0: all conversions in one grid (single plane everywhere)
    cvt_all<<<dim3(4096, 6), 256>>>(x, states, Wq, Wk, Wv, Wp,
        x1, st1, wq1, wk1, wv1, wp1);

    // Launch 1: Q (z<64) and K (z>=64) projections (M tiles=8, N tiles=4)
    gemm1<EPI_QK><<<dim3(4, 8, 128), 128, GEMM_SMEM>>>(
        x1, st1, DD, wq1, wk1, DD, DD,
        bq, bk, nullptr, nullptr, qk1, DD);

    // Launch 2: V projection -> V^T
    gemm1<EPI_VT><<<dim3(4, 8, 64), 128, GEMM_SMEM>>>(
        st1, nullptr, DD, wv1, nullptr, DD, DD,
        bv, nullptr, nullptr, nullptr, vt1, SLK);

    // Launch 3: scores = Q K^T * scale, masked (M=8 tiles, N=8 tiles)
    gemm1<EPI_SC><<<dim3(8, 8, 64), 128, GEMM_SMEM>>>(
        qk1, nullptr, DD,
        qk1 + (size_t)64 * SLQ * DD, nullptr, DD, DD,
        nullptr, nullptr, mask, Sf, nullptr, SLK);

    // Launch 4: softmax -> single-plane fp16 P
    softmax_hl<<<65536, 256>>>();

    // Launch 5 (profiled): ctx = P V
    gemm1<EPI_CTX><<<dim3(4, 8, 64), 128, GEMM_SMEM>>>(
        p1, nullptr, SLK, vt1, nullptr, SLK, SLK,
        nullptr, nullptr, nullptr, nullptr, c1, HD);

    // Launch 6: out = C Wp^T + bp (M=64 tiles, N=4 tiles)
    gemm1<EPI_OUT><<<dim3(4, 64, 1), 128, GEMM_SMEM>>>(
        c1, nullptr, HD, wp1, nullptr, HD, HD,
        bp, nullptr, nullptr, out, nullptr, DD);
}

// round 17
// speedup vs baseline: 1.9290x; 1.0126x over previous
#include <cuda_runtime.h>
#include <cuda_fp16.h>
#include <cstdint>

// Problem dims
#define NB 8
#define NH 8
#define SLQ 1024
#define SLK 1024
#define DD 512
#define HD 4096

using hf = __half;

// ---------------- device global scratch ----------------
__device__ hf g_x[(size_t)NB*SLQ*DD];
__device__ hf g_st[(size_t)NB*SLK*DD];
__device__ hf g_Wq[(size_t)NH*DD*DD];
__device__ hf g_Wk[(size_t)NH*DD*DD];
__device__ hf g_Wv[(size_t)NH*DD*DD];
__device__ hf g_Wp[(size_t)DD*HD];
__device__ hf g_QK[(size_t)128*SLQ*DD];    // single-plane Q (z<64), K (z>=64)
__device__ hf g_VT[(size_t)64*DD*SLK];
__device__ float g_S[(size_t)64*SLQ*SLK];
__device__ hf g_P[(size_t)64*SLQ*SLK];     // single-plane P
__device__ hf g_C[(size_t)NB*SLQ*HD];      // single-plane ctx

// ---------------- PTX helpers (baseline ISA only) ----------------
__device__ __forceinline__ uint32_t smem_u32(const void* p) {
    uint32_t a;
    asm("{ .reg .u64 t; cvta.to.shared.u64 t, %1; cvt.u32.u64 %0, t; }" : "=r"(a) : "l"(p));
    return a;
}
#define CP_ASYNC16(dst, src) \
    asm volatile("cp.async.cg.shared.global [%0], [%1], 16;" :: "r"(dst), "l"(src))
#define CP_COMMIT() asm volatile("cp.async.commit_group;" ::: "memory")
#define CP_WAIT2() asm volatile("cp.async.wait_group 2;" ::: "memory")
#define CP_WAIT0() asm volatile("cp.async.wait_group 0;" ::: "memory")

__device__ __forceinline__ void ldsm_x4(uint32_t* r, uint32_t addr) {
    asm volatile("ldmatrix.sync.aligned.m8n8.x4.shared.b16 {%0,%1,%2,%3}, [%4];"
        : "=r"(r[0]), "=r"(r[1]), "=r"(r[2]), "=r"(r[3]) : "r"(addr));
}
__device__ __forceinline__ void mma16816(float* d, const uint32_t* a, const uint32_t* b) {
    asm volatile("mma.sync.aligned.m16n8k16.row.col.f32.f16.f16.f32 "
        "{%0,%1,%2,%3}, {%4,%5,%6,%7}, {%8,%9}, {%0,%1,%2,%3};"
        : "+f"(d[0]), "+f"(d[1]), "+f"(d[2]), "+f"(d[3])
        : "r"(a[0]), "r"(a[1]), "r"(a[2]), "r"(a[3]), "r"(b[0]), "r"(b[1]));
}

// 64B-row swizzle: slot' = chunk ^ ((row>>1)&3), conflict-free for ldmatrix groups
__device__ __forceinline__ uint32_t swzoff(int row, int chunk) {
    return (uint32_t)row * 64u + (uint32_t)((chunk ^ ((row >> 1) & 3)) << 4);
}

// Tiles: CTA 128(M) x 128(N) x 32(K); 4 warps in 2(M) x 2(N), warp tile 64x64.
// __launch_bounds__(128,3) -> 3 CTAs/SM, 12 warps/SM.
// 4-stage cp.async pipeline: stage 16KB, 64KB/CTA (192KB/SM at 3 CTAs).
// Loop: wait_group 2 -> sync -> load(c+3) -> compute(c). Two loads always in
// flight; load(c+3) writes stage (c+3)%4 == (c-1)%4 whose readers finished
// before the barrier -> race-free.
#define OFF_B 8192
#define STAGE_B 16384
#define GEMM_SMEM 65536

// Epilogue IDs
#define EPI_QK  0  // dual-source, bias + single fp16, row-major
#define EPI_VT  1  // bias + single fp16, transposed (write V^T)
#define EPI_SC  2  // scale + mask -> fp32
#define EPI_CTX 3  // single fp16, row-major (head-concat via oOff)
#define EPI_OUT 4  // bias -> fp32

// Uniform 1-product GEMM: D = A*B^T (A, B single fp16), BK = 32
template<int EPI>
__global__ void __launch_bounds__(128, 3) gemm1(
    const hf* __restrict__ Ah, const hf* __restrict__ A2h, int lda,
    const hf* __restrict__ Bh, const hf* __restrict__ B2h, int ldb,
    int Ktot,
    const float* __restrict__ bias, const float* __restrict__ bias2,
    const int* __restrict__ mask,
    float* __restrict__ outf,
    hf* __restrict__ oh, int ldo)
{
    extern __shared__ char smem[];
    const uint32_t sb = smem_u32(smem);
    const int tid = threadIdx.x;
    const int wid = tid >> 5;
    const int lane = tid & 31;
    const int z = blockIdx.z;
    const int m0 = blockIdx.y * 128;
    const int n0 = blockIdx.x * 128;

    size_t aOff = 0, bOff = 0, oOff = 0, mOff = 0;
    if (EPI == EPI_QK) {
        const int zz = z & 63;
        if (z >= 64) { Ah = A2h; Bh = B2h; bias = bias2; }
        aOff = (size_t)(zz >> 3) * SLQ * DD;
        bOff = (size_t)(zz & 7) * DD * DD;
        oOff = (size_t)z * SLQ * DD;
    } else if (EPI == EPI_VT) {
        aOff = (size_t)(z >> 3) * SLQ * DD;
        bOff = (size_t)(z & 7) * DD * DD;
        oOff = (size_t)z * DD * SLK;
    } else if (EPI == EPI_SC) {
        aOff = (size_t)z * SLQ * DD;
        bOff = (size_t)z * SLK * DD;
        oOff = (size_t)z * SLQ * SLK;
        mOff = (size_t)(z >> 3) * SLQ * SLK;
    } else if (EPI == EPI_CTX) {
        aOff = (size_t)z * SLQ * SLK;
        bOff = (size_t)z * DD * SLK;
        oOff = (size_t)(z >> 3) * SLQ * HD + (size_t)(z & 7) * DD;
    }

    // ---- loader mapping: 128 threads; each: 4 A-chunks + 4 B-chunks (16B each)
    const int lc = tid & 3;     // 16B k-chunk (0..3)
    const int lr = tid >> 2;    // row 0..31 (rows lr + 32i)
    uint32_t soff[4];
    #pragma unroll
    for (int i = 0; i < 4; i++)
        soff[i] = swzoff(lr + 32 * i, lc);
    const hf* sA = Ah + aOff + (size_t)(m0 + lr) * lda + lc * 8;
    const hf* sB = Bh + bOff + (size_t)(n0 + lr) * ldb + lc * 8;
    const size_t r32a = (size_t)32 * lda;
    const size_t r32b = (size_t)32 * ldb;

    const int NCH = Ktot >> 5;  // BK = 32 (NCH >= 16 for all stages)

#define LOAD_CHUNK(stg, kt) do { \
    const uint32_t _b = sb + (stg) * STAGE_B; \
    _Pragma("unroll") \
    for (int i = 0; i < 4; i++) CP_ASYNC16(_b + soff[i],         sA + (kt) + (size_t)i * r32a); \
    _Pragma("unroll") \
    for (int i = 0; i < 4; i++) CP_ASYNC16(_b + OFF_B + soff[i], sB + (kt) + (size_t)i * r32b); \
    CP_COMMIT(); } while (0)

    // prologue: chunks 0,1,2 into stages 0,1,2
    LOAD_CHUNK(0, 0);
    LOAD_CHUNK(1, 32);
    LOAD_CHUNK(2, 64);

    // ---- compute mapping: warp grid 2(M) x 2(N), warp tile 64x64
    const int warpM = wid >> 1;      // 0..1
    const int warpN = wid & 1;       // 0..1
    const int grp = lane >> 3;
    const int l7  = lane & 7;
    const int arowb = warpM * 64 + ((grp & 1) << 3) + l7;   // + mt*16
    const int akc   = grp >> 1;                              // + ks*2
    const int browb = warpN * 64 + ((grp >> 1) << 3) + l7;  // + p*16
    const int bkc   = grp & 1;                               // + ks*2

    float acc[4][8][4];
    #pragma unroll
    for (int mt = 0; mt < 4; mt++)
        #pragma unroll
        for (int nt = 0; nt < 8; nt++)
            #pragma unroll
            for (int j = 0; j < 4; j++) acc[mt][nt][j] = 0.f;

    for (int c = 0; c < NCH; c++) {
        CP_WAIT2();          // <=2 groups outstanding -> chunk c landed
        __syncthreads();
        if (c + 3 < NCH)
            LOAD_CHUNK((c + 3) & 3, (size_t)(c + 3) * 32);
        else
            CP_COMMIT();     // empty group: uniform accounting near the tail

        const uint32_t st = sb + (c & 3) * STAGE_B;
        #pragma unroll
        for (int ks = 0; ks < 2; ks++) {
            uint32_t ah[4][4];
            #pragma unroll
            for (int mt = 0; mt < 4; mt++) {
                const uint32_t off = swzoff(arowb + mt * 16, akc + ks * 2);
                ldsm_x4(ah[mt], st + off);
            }
            #pragma unroll
            for (int p = 0; p < 4; p++) {
                uint32_t bh[4];
                const uint32_t off = swzoff(browb + p * 16, bkc + ks * 2);
                ldsm_x4(bh, st + OFF_B + off);
                #pragma unroll
                for (int mt = 0; mt < 4; mt++) {
                    #pragma unroll
                    for (int h = 0; h < 2; h++) {
                        mma16816(acc[mt][p * 2 + h], ah[mt], &bh[h * 2]);
                    }
                }
            }
        }
    }

    // ---------------- epilogue ----------------
    const int r4 = lane >> 2;
    const int c2 = (lane & 3) * 2;
    const int colb = n0 + warpN * 64 + c2;

    #pragma unroll
    for (int mt = 0; mt < 4; mt++) {
        #pragma unroll
        for (int rh = 0; rh < 2; rh++) {
            const int row = m0 + warpM * 64 + mt * 16 + rh * 8 + r4;
            if (EPI == EPI_QK || EPI == EPI_CTX) {
                const size_t rowbase = oOff + (size_t)row * ldo + colb;
                #pragma unroll
                for (int nt = 0; nt < 8; nt++) {
                    const int col = colb + nt * 8;
                    float v0 = acc[mt][nt][rh * 2 + 0];
                    float v1 = acc[mt][nt][rh * 2 + 1];
                    if (EPI == EPI_QK) { v0 += bias[col]; v1 += bias[col + 1]; }
                    hf h0 = __float2half_rn(v0);
                    hf h1 = __float2half_rn(v1);
                    uint32_t ph = (uint32_t)*(unsigned short*)&h0 | ((uint32_t)*(unsigned short*)&h1 << 16);
                    *(uint32_t*)(oh + rowbase + nt * 8) = ph;
                }
            } else if (EPI == EPI_VT) {
                #pragma unroll
                for (int nt = 0; nt < 8; nt++) {
                    const int col = colb + nt * 8;
                    float v0 = acc[mt][nt][rh * 2 + 0] + bias[col];
                    float v1 = acc[mt][nt][rh * 2 + 1] + bias[col + 1];
                    const size_t i0 = oOff + (size_t)col * SLK + row;
                    oh[i0] = __float2half_rn(v0);
                    oh[i0 + SLK] = __float2half_rn(v1);
                }
            } else if (EPI == EPI_SC) {
                const float scale = 0.044194173824159216f;  // 1/sqrt(512)
                const size_t rowbase = oOff + (size_t)row * SLK + colb;
                const int* mp = mask + mOff + (size_t)row * SLK + colb;
                #pragma unroll
                for (int nt = 0; nt < 8; nt++) {
                    int2 mk = *(const int2*)(mp + nt * 8);
                    float2 o;
                    o.x = mk.x ? acc[mt][nt][rh * 2 + 0] * scale : -1e30f;
                    o.y = mk.y ? acc[mt][nt][rh * 2 + 1] * scale : -1e30f;
                    *(float2*)(outf + rowbase + nt * 8) = o;
                }
            } else {  // EPI_OUT
                const size_t rowbase = (size_t)row * ldo + colb;
                #pragma unroll
                for (int nt = 0; nt < 8; nt++) {
                    const int col = colb + nt * 8;
                    float2 o;
                    o.x = acc[mt][nt][rh * 2 + 0] + bias[col];
                    o.y = acc[mt][nt][rh * 2 + 1] + bias[col + 1];
                    *(float2*)(outf + rowbase + nt * 8) = o;
                }
            }
        }
    }
}

// ---------------- fused fp32 -> fp16 conversion (single plane, all tensors) ----------------
__global__ void cvt_all(
    const float* __restrict__ x, const float* __restrict__ st,
    const float* __restrict__ wq, const float* __restrict__ wk,
    const float* __restrict__ wv, const float* __restrict__ wp,
    hf* x1, hf* st1, hf* wq1, hf* wk1, hf* wv1, hf* wp1)
{
    const int which = blockIdx.y;
    const float* s; hf* d; int n4;
    if (which == 0)      { s = x;  d = x1;  n4 = NB*SLQ*DD/4; }
    else if (which == 1) { s = st; d = st1; n4 = NB*SLK*DD/4; }
    else if (which == 2) { s = wq; d = wq1; n4 = NH*DD*DD/4; }
    else if (which == 3) { s = wk; d = wk1; n4 = NH*DD*DD/4; }
    else if (which == 4) { s = wv; d = wv1; n4 = NH*DD*DD/4; }
    else                 { s = wp; d = wp1; n4 = DD*HD/4; }
    int i = blockIdx.x * blockDim.x + threadIdx.x;
    if (i >= n4) return;
    float4 v = ((const float4*)s)[i];
    uint2 vh;
    unsigned short* ph = (unsigned short*)&vh;
    hf a = __float2half_rn(v.x), b = __float2half_rn(v.y);
    hf c = __float2half_rn(v.z), dd = __float2half_rn(v.w);
    ph[0] = *(unsigned short*)&a; ph[1] = *(unsigned short*)&b;
    ph[2] = *(unsigned short*)&c; ph[3] = *(unsigned short*)&dd;
    ((uint2*)d)[i] = vh;
}

// ---------------- softmax: warp-per-row, shuffle-only (no barriers) ----------------
__global__ void __launch_bounds__(256) softmax_hl()
{
    const int wid = threadIdx.x >> 5;
    const int lane = threadIdx.x & 31;
    const size_t row = (size_t)blockIdx.x * 8 + wid;
    const float4* p = (const float4*)(g_S + row * SLK);
    uint2* ph = (uint2*)(g_P + row * SLK);

    float4 v[8];
    float m = -1e30f;
    #pragma unroll
    for (int i = 0; i < 8; i++) {
        v[i] = p[i * 32 + lane];
        m = fmaxf(m, fmaxf(fmaxf(v[i].x, v[i].y), fmaxf(v[i].z, v[i].w)));
    }
    #pragma unroll
    for (int o = 16; o; o >>= 1) m = fmaxf(m, __shfl_xor_sync(0xffffffffu, m, o));

    float sum = 0.f;
    #pragma unroll
    for (int i = 0; i < 8; i++) {
        v[i].x = __expf(v[i].x - m); v[i].y = __expf(v[i].y - m);
        v[i].z = __expf(v[i].z - m); v[i].w = __expf(v[i].w - m);
        sum += (v[i].x + v[i].y) + (v[i].z + v[i].w);
    }
    #pragma unroll
    for (int o = 16; o; o >>= 1) sum += __shfl_xor_sync(0xffffffffu, sum, o);
    const float inv = 1.0f / sum;

    #pragma unroll
    for (int i = 0; i < 8; i++) {
        uint2 vh;
        unsigned short* qh = (unsigned short*)&vh;
        hf a = __float2half_rn(v[i].x * inv), b = __float2half_rn(v[i].y * inv);
        hf c = __float2half_rn(v[i].z * inv), d = __float2half_rn(v[i].w * inv);
        qh[0] = *(unsigned short*)&a; qh[1] = *(unsigned short*)&b;
        qh[2] = *(unsigned short*)&c; qh[3] = *(unsigned short*)&d;
        ph[i * 32 + lane] = vh;
    }
}

// ---------------- host launch ----------------
template<typename T>
static T* symaddr(const void* sym) {
    void* p = nullptr;
    cudaGetSymbolAddress(&p, sym);
    return (T*)p;
}

extern "C" void kernel_launch(void* const* d_in, const int* in_sizes, int n_in,
                              void* d_out, int out_size)
{
    const float* x      = (const float*)d_in[0];
    const float* states = (const float*)d_in[1];
    const int*   mask   = (const int*)  d_in[2];
    const float* Wq     = (const float*)d_in[3];
    const float* bq     = (const float*)d_in[4];
    const float* Wk     = (const float*)d_in[5];
    const float* bk     = (const float*)d_in[6];
    const float* Wv     = (const float*)d_in[7];
    const float* bv     = (const float*)d_in[8];
    const float* Wp     = (const float*)d_in[9];
    const float* bp     = (const float*)d_in[10];
    float* out = (float*)d_out;

    hf *x1 = symaddr<hf>(g_x);
    hf *st1 = symaddr<hf>(g_st);
    hf *wq1 = symaddr<hf>(g_Wq);
    hf *wk1 = symaddr<hf>(g_Wk);
    hf *wv1 = symaddr<hf>(g_Wv);
    hf *wp1 = symaddr<hf>(g_Wp);
    hf *qk1 = symaddr<hf>(g_QK);
    hf *vt1 = symaddr<hf>(g_VT);
    float *Sf = symaddr<float>(g_S);
    hf *p1 = symaddr<hf>(g_P);
    hf *c1 = symaddr<hf>(g_C);

    cudaFuncSetAttribute((const void*)gemm1<EPI_QK>,  cudaFuncAttributeMaxDynamicSharedMemorySize, GEMM_SMEM);
    cudaFuncSetAttribute((const void*)gemm1<EPI_VT>,  cudaFuncAttributeMaxDynamicSharedMemorySize, GEMM_SMEM);
    cudaFuncSetAttribute((const void*)gemm1<EPI_SC>,  cudaFuncAttributeMaxDynamicSharedMemorySize, GEMM_SMEM);
    cudaFuncSetAttribute((const void*)gemm1<EPI_CTX>, cudaFuncAttributeMaxDynamicSharedMemorySize, GEMM_SMEM);
    cudaFuncSetAttribute((const void*)gemm1<EPI_OUT>, cudaFuncAttributeMaxDynamicSharedMemorySize, GEMM_SMEM);

    // Launch 0: all conversions in one grid (single plane everywhere)
    cvt_all<<<dim3(4096, 6), 256>>>(x, states, Wq, Wk, Wv, Wp,
        x1, st1, wq1, wk1, wv1, wp1);

    // Launch 1: Q (z<64) and K (z>=64) projections (M tiles=8, N tiles=4)
    gemm1<EPI_QK><<<dim3(4, 8, 128), 128, GEMM_SMEM>>>(
        x1, st1, DD, wq1, wk1, DD, DD,
        bq, bk, nullptr, nullptr, qk1, DD);

    // Launch 2: V projection -> V^T
    gemm1<EPI_VT><<<dim3(4, 8, 64), 128, GEMM_SMEM>>>(
        st1, nullptr, DD, wv1, nullptr, DD, DD,
        bv, nullptr, nullptr, nullptr, vt1, SLK);

    // Launch 3: scores = Q K^T * scale, masked (M=8 tiles, N=8 tiles)
    gemm1<EPI_SC><<<dim3(8, 8, 64), 128, GEMM_SMEM>>>(
        qk1, nullptr, DD,
        qk1 + (size_t)64 * SLQ * DD, nullptr, DD, DD,
        nullptr, nullptr, mask, Sf, nullptr, SLK);

    // Launch 4: softmax (warp-per-row) -> single-plane fp16 P
    softmax_hl<<<8192, 256>>>();

    // Launch 5 (profiled): ctx = P V
    gemm1<EPI_CTX><<<dim3(4, 8, 64), 128, GEMM_SMEM>>>(
        p1, nullptr, SLK, vt1, nullptr, SLK, SLK,
        nullptr, nullptr, nullptr, nullptr, c1, HD);

    // Launch 6: out = C Wp^T + bp (M=64 tiles, N=4 tiles)
    gemm1<EPI_OUT><<<dim3(4, 64, 1), 128, GEMM_SMEM>>>(
        c1, nullptr, HD, wp1, nullptr, HD, HD,
        bp, nullptr, nullptr, out, nullptr, DD);
}